// round 3
// baseline (speedup 1.0000x reference)
#include <cuda_runtime.h>
#include <math.h>

// partial conv sums: [cg=4][b=16][co=3][128][128]
__device__ float g_part[4 * 16 * 3 * 128 * 128];

// ---------------- f32x2 helpers ----------------
__device__ __forceinline__ void ffma2(unsigned long long& d,
                                      unsigned long long a,
                                      unsigned long long b) {
    asm("fma.rn.f32x2 %0, %1, %2, %0;" : "+l"(d) : "l"(a), "l"(b));
}
__device__ __forceinline__ float sum2(unsigned long long v) {
    float a, b;
    asm("mov.b64 {%0, %1}, %2;" : "=f"(a), "=f"(b) : "l"(v));
    return a + b;
}

// =====================================================================
// Kernel 1: partial 3x3 conv, channel-pair interleaved smem (f32x2).
// Grid (16 tiles, 16 batch, 4 cg), block (32,8).
// Thread (tx,ty): column tx, rows 4*ty..4*ty+3 of a 32x32 tile.
// Whole warp = one row -> contiguous LDS.64, conflict-free.
// =====================================================================
#define HW 34   // halo width/height

__global__ __launch_bounds__(256, 3)
void conv_part(const float* __restrict__ fused,
               const float* __restrict__ wgt)   // [3,64,3,3]
{
    __shared__ float2 sv[4][HW][HW];    // 4 pair-planes, lanes = (chA, chB)
    __shared__ float2 swp[3 * 8 * 9];   // weight pairs [co][pair][tap]

    const int tile = blockIdx.x;
    const int b    = blockIdx.y;
    const int cg   = blockIdx.z;
    const int tlx  = (tile & 3) * 32;
    const int tly  = (tile >> 2) * 32;
    const int tx   = threadIdx.x;        // 0..31 column
    const int ty   = threadIdx.y;        // 0..7
    const int t    = ty * 32 + tx;
    const int r0   = 4 * ty;             // first output row (tile-local)

    // pack this cg's weight pairs from global (no prep kernel)
    for (int i = t; i < 3 * 8 * 9; i += 256) {
        int co = i / 72, rem = i - co * 72;
        int p  = rem / 9, k = rem - p * 9;
        int ci = cg * 16 + 2 * p;
        swp[i] = make_float2(wgt[(co * 64 + ci) * 9 + k],
                             wgt[(co * 64 + ci + 1) * 9 + k]);
    }
    const unsigned long long* swp64 = reinterpret_cast<const unsigned long long*>(swp);
    const unsigned long long* sv64  = reinterpret_cast<const unsigned long long*>(sv);

    unsigned long long acc[4][3];
    #pragma unroll
    for (int p = 0; p < 4; ++p)
        #pragma unroll
        for (int co = 0; co < 3; ++co) acc[p][co] = 0ull;

    const float* fb = fused + ((size_t)b * 64 + cg * 16) * (128 * 128);

    #pragma unroll 1
    for (int s = 0; s < 2; ++s) {       // 2 stages x 4 channel-pairs
        __syncthreads();
        // stage 4 pair-planes (8 channels), interleaved float2, zero-padded halo
        #pragma unroll 1
        for (int i = t; i < 4 * HW * HW; i += 256) {
            int pl  = i / (HW * HW);
            int rem = i - pl * (HW * HW);
            int r = rem / HW, c = rem - r * HW;
            int gy = tly - 1 + r, gx = tlx - 1 + c;
            float va = 0.f, vb = 0.f;
            if ((unsigned)gy < 128u && (unsigned)gx < 128u) {
                const float* pA = fb + (size_t)(8 * s + 2 * pl) * (128 * 128)
                                     + (size_t)gy * 128 + gx;
                va = pA[0];
                vb = pA[128 * 128];
            }
            sv[pl][r][c] = make_float2(va, vb);
        }
        __syncthreads();

        #pragma unroll
        for (int cp = 0; cp < 4; ++cp) {
            // window: sv rows r0..r0+5, cols tx..tx+2  (image rows r0-1.., cols tx-1..)
            unsigned long long win[6][3];
            #pragma unroll
            for (int r = 0; r < 6; ++r)
                #pragma unroll
                for (int dc = 0; dc < 3; ++dc)
                    win[r][dc] = sv64[(cp * HW + r0 + r) * HW + tx + dc];

            const int pairIdx = s * 4 + cp;
            #pragma unroll
            for (int co = 0; co < 3; ++co) {
                const unsigned long long* w9 = swp64 + (co * 8 + pairIdx) * 9;
                #pragma unroll
                for (int ky = 0; ky < 3; ++ky) {
                    #pragma unroll
                    for (int kx = 0; kx < 3; ++kx) {
                        unsigned long long w = w9[ky * 3 + kx];
                        ffma2(acc[0][co], win[0 + ky][kx], w);
                        ffma2(acc[1][co], win[1 + ky][kx], w);
                        ffma2(acc[2][co], win[2 + ky][kx], w);
                        ffma2(acc[3][co], win[3 + ky][kx], w);
                    }
                }
            }
        }
    }

    // epilogue: reduce f32x2 lanes, store partials (coalesced: tx contiguous)
    #pragma unroll
    for (int co = 0; co < 3; ++co) {
        size_t base = (((size_t)cg * 16 + b) * 3 + co) * (128 * 128)
                    + (size_t)(tly + r0) * 128 + (tlx + tx);
        #pragma unroll
        for (int p = 0; p < 4; ++p)
            g_part[base + (size_t)p * 128] = sum2(acc[p][co]);
    }
}

// =====================================================================
// Kernel 2: combine partials + bias + tanh, then fused double IWT.
// Thread: 2x2 block at 256-level -> 4x4 block of 512-level output.
// Grid (128, 48), block 128.
// =====================================================================
__global__ __launch_bounds__(128)
void iwt2_kernel(const float* __restrict__ hf1,   // [16,9,256,256]
                 const float* __restrict__ hf2,   // [16,9,128,128]
                 const float* __restrict__ bias,  // [3]
                 float* __restrict__ out)         // [16,3,512,512]
{
    const int t  = threadIdx.x;     // w128
    const int H  = blockIdx.x;      // h128
    const int bc = blockIdx.y;      // b*3+c
    const int b  = bc / 3, c = bc - 3 * b;

    size_t pidx = ((size_t)bc * 128 + H) * 128 + t;
    const size_t ps = (size_t)16 * 3 * 128 * 128;
    float p = g_part[pidx] + g_part[pidx + ps] +
              g_part[pidx + 2 * ps] + g_part[pidx + 3 * ps];
    const float ll = tanhf(p + bias[c]);

    size_t h2b = (((size_t)b * 9 + 3 * c) * 128 + H) * 128 + t;
    const float lh = hf2[h2b]                 * 2.f - 1.f;
    const float hl = hf2[h2b + 128 * 128]     * 2.f - 1.f;
    const float hh = hf2[h2b + 2 * 128 * 128] * 2.f - 1.f;

    float curr[2][2];
    #pragma unroll
    for (int dy = 0; dy < 2; ++dy) {
        float sp = dy ? 1.f : -1.f;
        #pragma unroll
        for (int dx = 0; dx < 2; ++dx) {
            float sq = dx ? 1.f : -1.f;
            curr[dy][dx] = 0.5f * (ll + sp * lh + sq * hl + (sp * sq) * hh);
        }
    }

    size_t h1b = (((size_t)b * 9 + 3 * c) * 256 + 2 * (size_t)H) * 256 + 2 * t;
    const size_t cs = (size_t)256 * 256;
    float2 A0 = *reinterpret_cast<const float2*>(hf1 + h1b);
    float2 B0 = *reinterpret_cast<const float2*>(hf1 + h1b + cs);
    float2 C0 = *reinterpret_cast<const float2*>(hf1 + h1b + 2 * cs);
    float2 A1 = *reinterpret_cast<const float2*>(hf1 + h1b + 256);
    float2 B1 = *reinterpret_cast<const float2*>(hf1 + h1b + cs + 256);
    float2 C1 = *reinterpret_cast<const float2*>(hf1 + h1b + 2 * cs + 256);

    size_t ob = ((size_t)bc * 512 + 4 * (size_t)H) * 512 + 4 * t;

    #pragma unroll
    for (int dy = 0; dy < 2; ++dy) {
        float2 Ap = dy ? A1 : A0;
        float2 Bp = dy ? B1 : B0;
        float2 Cp = dy ? C1 : C0;
        float4 row0, row1;
        #pragma unroll
        for (int dx = 0; dx < 2; ++dx) {
            float a  = (dx ? Ap.y : Ap.x) * 2.f - 1.f;
            float bb = (dx ? Bp.y : Bp.x) * 2.f - 1.f;
            float cc = (dx ? Cp.y : Cp.x) * 2.f - 1.f;
            float cu = curr[dy][dx];
            float o00 = 0.5f * (cu - a - bb + cc);
            float o01 = 0.5f * (cu - a + bb - cc);
            float o10 = 0.5f * (cu + a - bb - cc);
            float o11 = 0.5f * (cu + a + bb + cc);
            if (dx == 0) { row0.x = o00; row0.y = o01; row1.x = o10; row1.y = o11; }
            else         { row0.z = o00; row0.w = o01; row1.z = o10; row1.w = o11; }
        }
        *reinterpret_cast<float4*>(out + ob + (size_t)(2 * dy) * 512)     = row0;
        *reinterpret_cast<float4*>(out + ob + (size_t)(2 * dy + 1) * 512) = row1;
    }
}

// =====================================================================
extern "C" void kernel_launch(void* const* d_in, const int* in_sizes, int n_in,
                              void* d_out, int out_size)
{
    const float* fused  = (const float*)d_in[0];  // [16,64,128,128]
    const float* hf1    = (const float*)d_in[1];  // [16,9,256,256]
    const float* hf2    = (const float*)d_in[2];  // [16,9,128,128]
    const float* conv_w = (const float*)d_in[3];  // [3,64,3,3]
    const float* conv_b = (const float*)d_in[4];  // [3]
    float* out = (float*)d_out;                   // [16,3,512,512]

    dim3 g1(16, 16, 4), b1(32, 8);
    conv_part<<<g1, b1>>>(fused, conv_w);

    dim3 g2(128, 48), b2(128);
    iwt2_kernel<<<g2, b2>>>(hf1, hf2, conv_b, out);
}